// round 9
// baseline (speedup 1.0000x reference)
#include <cuda_runtime.h>
#include <cuda_fp16.h>
#include <cstdint>

#define N_TOK   2048
#define D_MODEL 1024
#define D_INT   512
#define NE      8
#define NPAIR   (N_TOK * 2)
#define NPAD    5120
#define KT1     16                // fc1 k-tiles (K=1024, BK=64)
#define KT2     8                 // fc2 k-tiles (K=512)

#define TILE_A      16384         // 128 rows x 128B fp16
#define TILE_B      16384
#define STAGE_BYTES (TILE_A + TILE_B)
#define NSTAGE      3
#define SMEM_SZ     (1024 + NSTAGE * STAGE_BYTES)   // 99328 -> 2 CTAs/SM

// ---- task queue ranges ----
#define TW1_0  160                // [0,160): x-conv; [160,416): w1-conv
#define TW2_0  416                // [416,544): w2-conv
#define TZ0    544                // [544,672): zero-out
#define TFC1   672                // [672,992): fc1 tiles (40 mt x 8 nb)
#define TFC2   992                // [992,1312): fc2 tiles
#define TTOT   1312
#define NGRID  296

// ---- scratch (allocation-free: __device__ globals) ----
__device__ int g_poff[NE + 1];
__device__ int g_cnt[NE];
__device__ int g_cur[NE];
__device__ int g_pair[NPAD];
__device__ int g_ticket;
__device__ int g_c_xw1;           // x+w1 conv done counter (target 416)
__device__ int g_c_wz;            // w2+zero done counter (target 256)
__device__ int g_done[64];        // per-mtile fc1 completion (target 8)
__device__ int g_nmt;
__device__ int g_mt_e[64];
__device__ int g_mt_rows[64];
__device__ __align__(16) char g_A1[(size_t)(NPAD / 128) * KT1 * TILE_A];  // 10MB
__device__ __align__(16) char g_B1[(size_t)NE * 8 * KT1 * TILE_B];        // 16MB
__device__ __align__(16) char g_A2[(size_t)(NPAD / 128) * KT2 * TILE_A];  // 5MB
__device__ __align__(16) char g_B2[(size_t)NE * 8 * KT2 * TILE_B];        // 8MB

// ================= asm helpers (sm_90-base PTX only) =================
__device__ __forceinline__ uint32_t smem_u32(const void* p) {
    uint32_t a;
    asm("{ .reg .u64 t; cvta.to.shared.u64 t, %1; cvt.u32.u64 %0, t; }" : "=r"(a) : "l"(p));
    return a;
}
__device__ __forceinline__ int ld_acq(const int* p) {
    int v;
    asm volatile("ld.acquire.gpu.global.b32 %0, [%1];" : "=r"(v) : "l"(p) : "memory");
    return v;
}
__device__ __forceinline__ void mbar_init(uint32_t a, uint32_t cnt) {
    asm volatile("mbarrier.init.shared::cta.b64 [%0], %1;" :: "r"(a), "r"(cnt) : "memory");
}
__device__ __forceinline__ void mbar_expect_tx(uint32_t a, uint32_t bytes) {
    asm volatile("mbarrier.arrive.expect_tx.shared::cta.b64 _, [%0], %1;"
                 :: "r"(a), "r"(bytes) : "memory");
}
__device__ __forceinline__ void mwait(uint32_t a, uint32_t ph) {
    asm volatile(
        "{\n\t.reg .pred P;\n"
        "W%=:\n\t"
        "mbarrier.try_wait.parity.acquire.cta.shared::cta.b64 P, [%0], %1, 0x989680;\n\t"
        "@P bra D%=;\n\t"
        "bra W%=;\n"
        "D%=:\n\t}"
        :: "r"(a), "r"(ph) : "memory");
}
__device__ __forceinline__ void bulk_g2s(uint32_t dst, const void* src, uint32_t bytes, uint32_t mbar) {
    asm volatile(
        "cp.async.bulk.shared::cluster.global.mbarrier::complete_tx::bytes [%0], [%1], %2, [%3];"
        :: "r"(dst), "l"(src), "r"(bytes), "r"(mbar) : "memory");
}
__device__ __forceinline__ void ldsm4(uint32_t* r, uint32_t a) {
    asm volatile("ldmatrix.sync.aligned.m8n8.x4.shared.b16 {%0,%1,%2,%3}, [%4];"
                 : "=r"(r[0]), "=r"(r[1]), "=r"(r[2]), "=r"(r[3]) : "r"(a));
}
__device__ __forceinline__ void mma_f16(float* d, const uint32_t* a, const uint32_t* b) {
    asm volatile(
        "mma.sync.aligned.m16n8k16.row.col.f32.f16.f16.f32 "
        "{%0,%1,%2,%3}, {%4,%5,%6,%7}, {%8,%9}, {%0,%1,%2,%3};"
        : "+f"(d[0]), "+f"(d[1]), "+f"(d[2]), "+f"(d[3])
        : "r"(a[0]), "r"(a[1]), "r"(a[2]), "r"(a[3]), "r"(b[0]), "r"(b[1]));
}
__device__ __forceinline__ uint32_t swz128(int row, int chunk) {
    return (uint32_t)(row * 128 + ((chunk ^ (row & 7)) << 4));
}

// ================= setup =================
__global__ void k_setup(const int* __restrict__ counts, const int* __restrict__ indices) {
    int tid = threadIdx.x;
    if (tid == 0) {
        g_ticket = 0;
        g_c_xw1 = 0;
        g_c_wz = 0;
        int o = 0;
        g_poff[0] = 0;
        int mt = 0;
        for (int e = 0; e < NE; e++) {
            int c = counts[e];
            g_cnt[e] = c;
            g_cur[e] = o;
            int tiles = (c + 127) >> 7;
            for (int k = 0; k < tiles; k++) {
                g_mt_e[mt] = e;
                int rr = c - k * 128;
                g_mt_rows[mt] = rr > 128 ? 128 : rr;
                mt++;
            }
            o += tiles << 7;
            g_poff[e + 1] = o;
        }
        g_nmt = mt;
    }
    for (int i = tid; i < 64; i += 256) g_done[i] = 0;
    for (int i = tid; i < NPAD; i += 256) g_pair[i] = -1;
    __syncthreads();
    for (int p = tid; p < NPAIR; p += 256) {
        int e = indices[p];
        int pos = atomicAdd(&g_cur[e], 1);
        g_pair[pos] = p;
    }
}

// ================= GEMM tile; mbarriers init'd ONCE, slot/ph persist ======
__device__ __forceinline__ void do_gemm(bool fc1, int KT, int mt, int nb,
                                        const float* __restrict__ wts,
                                        float* __restrict__ out,
                                        uint32_t sb, int tid,
                                        int& slot, int& ph) {
    int lane = tid & 31, wid = tid >> 5;
    int e = g_mt_e[mt];
    int rows = g_mt_rows[mt];
    const char* Abuf = fc1 ? g_A1 : g_A2;
    const char* Bbuf = fc1 ? g_B1 : g_B2;
    size_t atile = (size_t)mt * KT;
    size_t btile = (size_t)(e * 8 + nb) * KT;
    const int n0 = nb * 128;
    const int arow0 = mt * 128;

    // prologue: fill the NSTAGE slots starting from current persistent slot
    if (tid == 0) {
#pragma unroll
        for (int s = 0; s < NSTAGE; s++) {
            int sl = slot + s;
            if (sl >= NSTAGE) sl -= NSTAGE;
            mbar_expect_tx(sb + sl * 8, STAGE_BYTES);
            uint32_t d = sb + 1024 + sl * STAGE_BYTES;
            bulk_g2s(d,          Abuf + (atile + s) * TILE_A, TILE_A, sb + sl * 8);
            bulk_g2s(d + TILE_A, Bbuf + (btile + s) * TILE_B, TILE_B, sb + sl * 8);
        }
    }

    int wm = wid & 1, wn = wid >> 1;
    int m_off = wm * 64, n_off = wn * 32;

    float acc[4][4][4];
#pragma unroll
    for (int i = 0; i < 4; i++)
#pragma unroll
        for (int j = 0; j < 4; j++)
#pragma unroll
            for (int q = 0; q < 4; q++) acc[i][j][q] = 0.f;

    int arow_l = m_off + (lane & 15);
    int akoff  = lane >> 4;
    int brow_l = n_off + (lane & 7) + ((lane >> 4) << 3);
    int bkoff  = (lane >> 3) & 1;

    for (int kt = 0; kt < KT; kt++) {
        mwait(sb + slot * 8, ph);
        uint32_t base = sb + 1024 + slot * STAGE_BYTES;
#pragma unroll
        for (int ks = 0; ks < 4; ks++) {
            uint32_t ahf[4][4];
            int ak = ks * 2 + akoff;
#pragma unroll
            for (int mf = 0; mf < 4; mf++)
                ldsm4(ahf[mf], base + swz128(arow_l + mf * 16, ak));
            int bk = ks * 2 + bkoff;
#pragma unroll
            for (int ng = 0; ng < 2; ng++) {
                uint32_t bf[4];
                ldsm4(bf, base + TILE_A + swz128(brow_l + ng * 16, bk));
#pragma unroll
                for (int mf = 0; mf < 4; mf++) {
                    mma_f16(acc[mf][2 * ng],     ahf[mf], &bf[0]);
                    mma_f16(acc[mf][2 * ng + 1], ahf[mf], &bf[2]);
                }
            }
        }
        __syncthreads();
        if (tid == 0 && kt + NSTAGE < KT) {
            mbar_expect_tx(sb + slot * 8, STAGE_BYTES);
            bulk_g2s(base,          Abuf + (atile + kt + NSTAGE) * TILE_A, TILE_A, sb + slot * 8);
            bulk_g2s(base + TILE_A, Bbuf + (btile + kt + NSTAGE) * TILE_B, TILE_B, sb + slot * 8);
        }
        if (++slot == NSTAGE) { slot = 0; ph ^= 1; }
    }

    int rq = lane >> 2, cq = lane & 3;
#pragma unroll
    for (int mf = 0; mf < 4; mf++) {
#pragma unroll
        for (int half = 0; half < 2; half++) {
            int mloc = m_off + mf * 16 + rq + half * 8;
            if (mloc >= rows) continue;
            if (fc1) {
                size_t trow = (size_t)mt * KT2;
#pragma unroll
                for (int nt = 0; nt < 4; nt++) {
                    float y = acc[mf][nt][half * 2];
                    float z = acc[mf][nt][half * 2 + 1];
                    float a = y * z * (1.f / (1.f + __expf(-z)));
                    int j = ((n0 + n_off + nt * 8) >> 1) + cq;
                    char* p = g_A2 + (trow + (j >> 6)) * TILE_A
                                  + swz128(mloc, (j >> 3) & 7) + (j & 7) * 2;
                    *(__half*)p = __float2half_rn(a);
                }
            } else {
                int pr = g_pair[arow0 + mloc];
                float w = wts[pr];
                float* ob = out + (size_t)(pr >> 1) * D_MODEL;
#pragma unroll
                for (int nt = 0; nt < 4; nt++) {
                    int nc = n0 + n_off + nt * 8 + cq * 2;
                    atomicAdd(ob + nc,     w * acc[mf][nt][half * 2]);
                    atomicAdd(ob + nc + 1, w * acc[mf][nt][half * 2 + 1]);
                }
            }
        }
    }
}

// ================= persistent worker =================
__global__ __launch_bounds__(256, 2) void k_persist(
    const float* __restrict__ x, const float* __restrict__ w1f,
    const float* __restrict__ w2f, const float* __restrict__ wts,
    float* __restrict__ out)
{
    extern __shared__ __align__(128) char smem[];
    __shared__ int s_task;
    uint32_t sb = smem_u32(smem);
    int tid = threadIdx.x;
    int slot = 0, ph = 0;          // persistent pipeline state (init ONCE)

    if (tid < NSTAGE) mbar_init(sb + tid * 8, 1);
    __syncthreads();
    if (tid == 0)
        asm volatile("fence.proxy.async.shared::cta;" ::: "memory");
    __syncthreads();

    for (;;) {
        __syncthreads();
        if (tid == 0) s_task = atomicAdd(&g_ticket, 1);
        __syncthreads();
        int t = s_task;
        if (t >= TTOT) return;

        if (t < TW1_0) {
            // ---- x conversion: NPAD*128 uint4 items ----
            int base = t * 4096;
#pragma unroll
            for (int it = 0; it < 16; it++) {
                int gid = base + it * 256 + tid;
                int s = gid >> 7;
                int k8 = gid & 127;
                char* dst = g_A1 + (size_t)((s >> 7) * KT1 + (k8 >> 3)) * TILE_A
                                 + swz128(s & 127, k8 & 7);
                int pr = g_pair[s];
                if (pr < 0) {
                    *(uint4*)dst = make_uint4(0, 0, 0, 0);
                    continue;
                }
                const float* sp = x + (size_t)(pr >> 1) * D_MODEL + k8 * 8;
                float f[8];
                *(float4*)&f[0] = *(const float4*)sp;
                *(float4*)&f[4] = *(const float4*)(sp + 4);
                __half h[8];
#pragma unroll
                for (int i = 0; i < 8; i++) h[i] = __float2half_rn(f[i]);
                *(uint4*)dst = *(uint4*)h;
            }
            __threadfence();
            __syncthreads();
            if (tid == 0) atomicAdd(&g_c_xw1, 1);
        } else if (t < TW2_0) {
            // ---- w1 conversion: NE*1024*128 ----
            int base = (t - TW1_0) * 4096;
#pragma unroll
            for (int it = 0; it < 16; it++) {
                int gid = base + it * 256 + tid;
                int e = gid >> 17;
                int rem = gid & 131071;
                int n = rem >> 7;
                int k8 = rem & 127;
                int j = n >> 1, g = n & 1;
                const float* sp = w1f + (size_t)e * (2 * D_INT * D_MODEL)
                                      + (size_t)(g * D_INT + j) * D_MODEL + k8 * 8;
                float f[8];
                *(float4*)&f[0] = *(const float4*)sp;
                *(float4*)&f[4] = *(const float4*)(sp + 4);
                __half h[8];
#pragma unroll
                for (int i = 0; i < 8; i++) h[i] = __float2half_rn(f[i]);
                char* dst = g_B1 + (size_t)((e * 8 + (n >> 7)) * KT1 + (k8 >> 3)) * TILE_B
                                + swz128(n & 127, k8 & 7);
                *(uint4*)dst = *(uint4*)h;
            }
            __threadfence();
            __syncthreads();
            if (tid == 0) atomicAdd(&g_c_xw1, 1);
        } else if (t < TZ0) {
            // ---- w2 conversion: NE*1024*64 ----
            int base = (t - TW2_0) * 4096;
#pragma unroll
            for (int it = 0; it < 16; it++) {
                int gid = base + it * 256 + tid;
                int ee = gid >> 16;
                int rem = gid & 65535;
                int n = rem >> 6;
                int k8 = rem & 63;
                const float* sp = w2f + (size_t)ee * (D_MODEL * D_INT) + (size_t)n * D_INT + k8 * 8;
                float f[8];
                *(float4*)&f[0] = *(const float4*)sp;
                *(float4*)&f[4] = *(const float4*)(sp + 4);
                __half h[8];
#pragma unroll
                for (int q = 0; q < 8; q++) h[q] = __float2half_rn(f[q]);
                char* dst = g_B2 + (size_t)((ee * 8 + (n >> 7)) * KT2 + (k8 >> 3)) * TILE_B
                                + swz128(n & 127, k8 & 7);
                *(uint4*)dst = *(uint4*)h;
            }
            __threadfence();
            __syncthreads();
            if (tid == 0) atomicAdd(&g_c_wz, 1);
        } else if (t < TFC1) {
            // ---- zero out ----
            int base = (t - TZ0) * 4096;
#pragma unroll
            for (int it = 0; it < 16; it++) {
                int gid = base + it * 256 + tid;
                ((float4*)out)[gid] = make_float4(0.f, 0.f, 0.f, 0.f);
            }
            __threadfence();
            __syncthreads();
            if (tid == 0) atomicAdd(&g_c_wz, 1);
        } else if (t < TFC2) {
            int ti = t - TFC1, mt = ti >> 3, nb = ti & 7;
            if (mt < g_nmt) {
                if (tid == 0)
                    while (ld_acq(&g_c_xw1) != 416) __nanosleep(64);
                __syncthreads();
                __threadfence();
                do_gemm(true, KT1, mt, nb, wts, out, sb, tid, slot, ph);
                __threadfence();
                __syncthreads();
                if (tid == 0) atomicAdd(&g_done[mt], 1);
            }
        } else {
            int ti = t - TFC2, mt = ti >> 3, nb = ti & 7;
            if (mt < g_nmt) {
                if (tid == 0) {
                    while (ld_acq(&g_c_wz) != 256) __nanosleep(64);
                    while (ld_acq(&g_done[mt]) != 8) __nanosleep(64);
                }
                __syncthreads();
                __threadfence();
                do_gemm(false, KT2, mt, nb, wts, out, sb, tid, slot, ph);
            }
        }
    }
}

// ================= host =================
extern "C" void kernel_launch(void* const* d_in, const int* in_sizes, int n_in,
                              void* d_out, int out_size) {
    const float* x      = (const float*)d_in[0];
    const float* wts    = (const float*)d_in[1];
    const int*   idx    = (const int*)d_in[2];
    const int*   counts = (const int*)d_in[3];
    const float* fc1w   = (const float*)d_in[4];
    const float* fc2w   = (const float*)d_in[5];
    float* out = (float*)d_out;

    cudaFuncSetAttribute(k_persist,
                         cudaFuncAttributeMaxDynamicSharedMemorySize, SMEM_SZ);

    k_setup<<<1, 256>>>(counts, idx);
    k_persist<<<NGRID, 256, SMEM_SZ>>>(x, fc1w, fc2w, wts, out);
}

// round 10
// speedup vs baseline: 1.2764x; 1.2764x over previous
#include <cuda_runtime.h>
#include <cuda_fp16.h>
#include <cstdint>

#define N_TOK   2048
#define D_MODEL 1024
#define D_INT   512
#define NE      8
#define NPAIR   (N_TOK * 2)
#define NPAD    5120
#define KT1     16                // fc1 k-tiles (K=1024, BK=64)
#define KT2     8                 // fc2 k-tiles (K=512)

#define TILE_A      16384         // 128 rows x 128B fp16
#define TILE_B      16384
#define STAGE_BYTES (TILE_A + TILE_B)
#define NSTAGE      2
#define SMEM_SZ     (1024 + NSTAGE * STAGE_BYTES)   // 66560 -> 2 CTAs/SM

// ---- task queue: [0] setup | w1 | w2 | zero | x | fc1 | fc2 ----
#define T_W1   1
#define T_W2   257
#define T_Z    385
#define T_X    513
#define T_FC1  673
#define T_FC2  993
#define TTOT   1313
#define NGRID  296

// ---- scratch (allocation-free; all zero-init at load, self-reset at exit) --
__device__ int g_pair[NPAD];
__device__ int g_ticket;
__device__ int g_c_ax;            // x+w1 conv done (target 416)
__device__ int g_c_wz;            // w2+zero done (target 256)
__device__ int g_setup;
__device__ int g_exit;
__device__ int g_done[64];
__device__ int g_nmt;
__device__ int g_mt_e[64];
__device__ int g_mt_rows[64];
__device__ __align__(16) char g_A1[(size_t)(NPAD / 128) * KT1 * TILE_A];
__device__ __align__(16) char g_B1[(size_t)NE * 8 * KT1 * TILE_B];
__device__ __align__(16) char g_A2[(size_t)(NPAD / 128) * KT2 * TILE_A];
__device__ __align__(16) char g_B2[(size_t)NE * 8 * KT2 * TILE_B];

// ================= asm helpers (sm_90-base PTX only) =================
__device__ __forceinline__ uint32_t smem_u32(const void* p) {
    uint32_t a;
    asm("{ .reg .u64 t; cvta.to.shared.u64 t, %1; cvt.u32.u64 %0, t; }" : "=r"(a) : "l"(p));
    return a;
}
__device__ __forceinline__ int ld_acq(const int* p) {
    int v;
    asm volatile("ld.acquire.gpu.global.b32 %0, [%1];" : "=r"(v) : "l"(p) : "memory");
    return v;
}
__device__ __forceinline__ void mbar_init(uint32_t a, uint32_t cnt) {
    asm volatile("mbarrier.init.shared::cta.b64 [%0], %1;" :: "r"(a), "r"(cnt) : "memory");
}
__device__ __forceinline__ void mbar_expect_tx(uint32_t a, uint32_t bytes) {
    asm volatile("mbarrier.arrive.expect_tx.shared::cta.b64 _, [%0], %1;"
                 :: "r"(a), "r"(bytes) : "memory");
}
__device__ __forceinline__ void mwait(uint32_t a, uint32_t ph) {
    asm volatile(
        "{\n\t.reg .pred P;\n"
        "W%=:\n\t"
        "mbarrier.try_wait.parity.acquire.cta.shared::cta.b64 P, [%0], %1, 0x989680;\n\t"
        "@P bra D%=;\n\t"
        "bra W%=;\n"
        "D%=:\n\t}"
        :: "r"(a), "r"(ph) : "memory");
}
__device__ __forceinline__ void bulk_g2s(uint32_t dst, const void* src, uint32_t bytes, uint32_t mbar) {
    asm volatile(
        "cp.async.bulk.shared::cluster.global.mbarrier::complete_tx::bytes [%0], [%1], %2, [%3];"
        :: "r"(dst), "l"(src), "r"(bytes), "r"(mbar) : "memory");
}
__device__ __forceinline__ void ldsm4(uint32_t* r, uint32_t a) {
    asm volatile("ldmatrix.sync.aligned.m8n8.x4.shared.b16 {%0,%1,%2,%3}, [%4];"
                 : "=r"(r[0]), "=r"(r[1]), "=r"(r[2]), "=r"(r[3]) : "r"(a));
}
__device__ __forceinline__ void mma_f16(float* d, const uint32_t* a, const uint32_t* b) {
    asm volatile(
        "mma.sync.aligned.m16n8k16.row.col.f32.f16.f16.f32 "
        "{%0,%1,%2,%3}, {%4,%5,%6,%7}, {%8,%9}, {%0,%1,%2,%3};"
        : "+f"(d[0]), "+f"(d[1]), "+f"(d[2]), "+f"(d[3])
        : "r"(a[0]), "r"(a[1]), "r"(a[2]), "r"(a[3]), "r"(b[0]), "r"(b[1]));
}
__device__ __forceinline__ uint32_t swz128(int row, int chunk) {
    return (uint32_t)(row * 128 + ((chunk ^ (row & 7)) << 4));
}

// ================= GEMM tile; compile-time KT/FC1; NSTAGE=2 ================
// Per-task mbarrier use count = KT/2 per slot (even) -> every task starts with
// slot 0 / phase 0. Static slot/phase inside the fully unrolled k-loop.
template<int KT, bool FC1>
__device__ __forceinline__ void do_gemm(int mt, int nb,
                                        const float* __restrict__ wts,
                                        float* __restrict__ out,
                                        uint32_t sb, int tid) {
    int lane = tid & 31, wid = tid >> 5;
    int e = g_mt_e[mt];
    int rows = g_mt_rows[mt];
    const char* Abuf = FC1 ? g_A1 : g_A2;
    const char* Bbuf = FC1 ? g_B1 : g_B2;
    size_t atile = (size_t)mt * KT;
    size_t btile = (size_t)(e * 8 + nb) * KT;
    const int n0 = nb * 128;
    const int arow0 = mt * 128;

    if (tid == 0) {
#pragma unroll
        for (int s = 0; s < NSTAGE; s++) {
            mbar_expect_tx(sb + s * 8, STAGE_BYTES);
            uint32_t d = sb + 1024 + s * STAGE_BYTES;
            bulk_g2s(d,          Abuf + (atile + s) * TILE_A, TILE_A, sb + s * 8);
            bulk_g2s(d + TILE_A, Bbuf + (btile + s) * TILE_B, TILE_B, sb + s * 8);
        }
    }

    int wm = wid & 1, wn = wid >> 1;
    int m_off = wm * 64, n_off = wn * 32;

    float acc[4][4][4];
#pragma unroll
    for (int i = 0; i < 4; i++)
#pragma unroll
        for (int j = 0; j < 4; j++)
#pragma unroll
            for (int q = 0; q < 4; q++) acc[i][j][q] = 0.f;

    int arow_l = m_off + (lane & 15);
    int akoff  = lane >> 4;
    int brow_l = n_off + (lane & 7) + ((lane >> 4) << 3);
    int bkoff  = (lane >> 3) & 1;

#pragma unroll
    for (int kt = 0; kt < KT; kt++) {
        const int slot = kt & 1;
        const int ph = (kt >> 1) & 1;
        mwait(sb + slot * 8, ph);
        uint32_t base = sb + 1024 + slot * STAGE_BYTES;
#pragma unroll
        for (int ks = 0; ks < 4; ks++) {
            uint32_t ahf[4][4];
            int ak = ks * 2 + akoff;
#pragma unroll
            for (int mf = 0; mf < 4; mf++)
                ldsm4(ahf[mf], base + swz128(arow_l + mf * 16, ak));
            int bk = ks * 2 + bkoff;
#pragma unroll
            for (int ng = 0; ng < 2; ng++) {
                uint32_t bf[4];
                ldsm4(bf, base + TILE_A + swz128(brow_l + ng * 16, bk));
#pragma unroll
                for (int mf = 0; mf < 4; mf++) {
                    mma_f16(acc[mf][2 * ng],     ahf[mf], &bf[0]);
                    mma_f16(acc[mf][2 * ng + 1], ahf[mf], &bf[2]);
                }
            }
        }
        __syncthreads();
        if (kt + NSTAGE < KT) {
            if (tid == 0) {
                mbar_expect_tx(sb + slot * 8, STAGE_BYTES);
                bulk_g2s(base,          Abuf + (atile + kt + NSTAGE) * TILE_A, TILE_A, sb + slot * 8);
                bulk_g2s(base + TILE_A, Bbuf + (btile + kt + NSTAGE) * TILE_B, TILE_B, sb + slot * 8);
            }
        }
    }

    int rq = lane >> 2, cq = lane & 3;
#pragma unroll
    for (int mf = 0; mf < 4; mf++) {
#pragma unroll
        for (int half = 0; half < 2; half++) {
            int mloc = m_off + mf * 16 + rq + half * 8;
            if (mloc >= rows) continue;
            if (FC1) {
                size_t trow = (size_t)mt * KT2;
#pragma unroll
                for (int nt = 0; nt < 4; nt++) {
                    float y = acc[mf][nt][half * 2];
                    float z = acc[mf][nt][half * 2 + 1];
                    float a = y * z * (1.f / (1.f + __expf(-z)));
                    int j = ((n0 + n_off + nt * 8) >> 1) + cq;
                    char* p = g_A2 + (trow + (j >> 6)) * TILE_A
                                  + swz128(mloc, (j >> 3) & 7) + (j & 7) * 2;
                    *(__half*)p = __float2half_rn(a);
                }
            } else {
                int pr = g_pair[arow0 + mloc];
                float w = wts[pr];
                float* ob = out + (size_t)(pr >> 1) * D_MODEL;
#pragma unroll
                for (int nt = 0; nt < 4; nt++) {
                    int nc = n0 + n_off + nt * 8 + cq * 2;
                    atomicAdd(ob + nc,     w * acc[mf][nt][half * 2]);
                    atomicAdd(ob + nc + 1, w * acc[mf][nt][half * 2 + 1]);
                }
            }
        }
    }
}

// ================= single persistent kernel =================
__global__ __launch_bounds__(256, 2) void k_persist(
    const float* __restrict__ x, const float* __restrict__ w1f,
    const float* __restrict__ w2f, const float* __restrict__ wts,
    const int* __restrict__ indices, const int* __restrict__ counts,
    float* __restrict__ out)
{
    extern __shared__ __align__(128) char smem[];
    __shared__ int s_task;
    __shared__ int s_off[NE];
    __shared__ int s_cur[NE];
    uint32_t sb = smem_u32(smem);
    int tid = threadIdx.x;

    if (tid < NSTAGE) mbar_init(sb + tid * 8, 1);
    __syncthreads();
    if (tid == 0)
        asm volatile("fence.proxy.async.shared::cta;" ::: "memory");
    __syncthreads();

    for (;;) {
        __syncthreads();
        if (tid == 0) s_task = atomicAdd(&g_ticket, 1);
        __syncthreads();
        int t = s_task;

        if (t >= TTOT) {
            // last CTA out resets all state for the next invocation
            __syncthreads();
            if (tid == 0) {
                __threadfence();
                int old = atomicAdd(&g_exit, 1);
                if (old == NGRID - 1) {
                    g_ticket = 0; g_c_ax = 0; g_c_wz = 0; g_setup = 0; g_exit = 0;
                    for (int i = 0; i < 64; i++) g_done[i] = 0;
                    __threadfence();
                }
            }
            return;
        }

        if (t == 0) {
            // ---- setup: mtile table + pair scatter (smem cursors) ----
            if (tid == 0) {
                int o = 0, mt = 0;
                for (int e = 0; e < NE; e++) {
                    int c = counts[e];
                    s_off[e] = o;
                    int tiles = (c + 127) >> 7;
                    for (int k = 0; k < tiles; k++) {
                        g_mt_e[mt] = e;
                        int rr = c - k * 128;
                        g_mt_rows[mt] = rr > 128 ? 128 : rr;
                        mt++;
                    }
                    o += tiles << 7;
                }
                g_nmt = mt;
            }
            for (int i = tid; i < NPAD; i += 256) g_pair[i] = -1;
            __syncthreads();
            if (tid < NE) s_cur[tid] = s_off[tid];
            __syncthreads();
            for (int p = tid; p < NPAIR; p += 256) {
                int e = indices[p];
                int pos = atomicAdd(&s_cur[e], 1);
                g_pair[pos] = p;
            }
            __threadfence();
            __syncthreads();
            if (tid == 0) atomicExch(&g_setup, 1);
        } else if (t < T_W2) {
            // ---- w1 conversion (no deps): NE*1024*128 gids ----
            int base = (t - T_W1) * 4096;
#pragma unroll
            for (int it = 0; it < 16; it++) {
                int gid = base + it * 256 + tid;
                int e = gid >> 17;
                int rem = gid & 131071;
                int n = rem >> 7;
                int k8 = rem & 127;
                int j = n >> 1, g = n & 1;
                const float* sp = w1f + (size_t)e * (2 * D_INT * D_MODEL)
                                      + (size_t)(g * D_INT + j) * D_MODEL + k8 * 8;
                float f[8];
                *(float4*)&f[0] = *(const float4*)sp;
                *(float4*)&f[4] = *(const float4*)(sp + 4);
                __half h[8];
#pragma unroll
                for (int i = 0; i < 8; i++) h[i] = __float2half_rn(f[i]);
                char* dst = g_B1 + (size_t)((e * 8 + (n >> 7)) * KT1 + (k8 >> 3)) * TILE_B
                                + swz128(n & 127, k8 & 7);
                *(uint4*)dst = *(uint4*)h;
            }
            __threadfence();
            __syncthreads();
            if (tid == 0) atomicAdd(&g_c_ax, 1);
        } else if (t < T_Z) {
            // ---- w2 conversion: NE*1024*64 gids ----
            int base = (t - T_W2) * 4096;
#pragma unroll
            for (int it = 0; it < 16; it++) {
                int gid = base + it * 256 + tid;
                int ee = gid >> 16;
                int rem = gid & 65535;
                int n = rem >> 6;
                int k8 = rem & 63;
                const float* sp = w2f + (size_t)ee * (D_MODEL * D_INT) + (size_t)n * D_INT + k8 * 8;
                float f[8];
                *(float4*)&f[0] = *(const float4*)sp;
                *(float4*)&f[4] = *(const float4*)(sp + 4);
                __half h[8];
#pragma unroll
                for (int q = 0; q < 8; q++) h[q] = __float2half_rn(f[q]);
                char* dst = g_B2 + (size_t)((ee * 8 + (n >> 7)) * KT2 + (k8 >> 3)) * TILE_B
                                + swz128(n & 127, k8 & 7);
                *(uint4*)dst = *(uint4*)h;
            }
            __threadfence();
            __syncthreads();
            if (tid == 0) atomicAdd(&g_c_wz, 1);
        } else if (t < T_X) {
            // ---- zero out ----
            int base = (t - T_Z) * 4096;
#pragma unroll
            for (int it = 0; it < 16; it++) {
                int gid = base + it * 256 + tid;
                ((float4*)out)[gid] = make_float4(0.f, 0.f, 0.f, 0.f);
            }
            __threadfence();
            __syncthreads();
            if (tid == 0) atomicAdd(&g_c_wz, 1);
        } else if (t < T_FC1) {
            // ---- x conversion (needs setup) ----
            if (tid == 0)
                while (ld_acq(&g_setup) == 0) __nanosleep(64);
            __syncthreads();
            int base = (t - T_X) * 4096;
#pragma unroll
            for (int it = 0; it < 16; it++) {
                int gid = base + it * 256 + tid;
                int s = gid >> 7;
                int k8 = gid & 127;
                char* dst = g_A1 + (size_t)((s >> 7) * KT1 + (k8 >> 3)) * TILE_A
                                 + swz128(s & 127, k8 & 7);
                int pr = g_pair[s];
                if (pr < 0) {
                    *(uint4*)dst = make_uint4(0, 0, 0, 0);
                    continue;
                }
                const float* sp = x + (size_t)(pr >> 1) * D_MODEL + k8 * 8;
                float f[8];
                *(float4*)&f[0] = *(const float4*)sp;
                *(float4*)&f[4] = *(const float4*)(sp + 4);
                __half h[8];
#pragma unroll
                for (int i = 0; i < 8; i++) h[i] = __float2half_rn(f[i]);
                *(uint4*)dst = *(uint4*)h;
            }
            __threadfence();
            __syncthreads();
            if (tid == 0) atomicAdd(&g_c_ax, 1);
        } else if (t < T_FC2) {
            int ti = t - T_FC1, mt = ti >> 3, nb = ti & 7;
            if (mt < ld_acq(&g_nmt) || mt < 40) {   // g_nmt valid only post-setup
                // wait all x+w1 conversions (implies setup done)
                if (tid == 0)
                    while (ld_acq(&g_c_ax) != 416) __nanosleep(64);
                __syncthreads();
                if (mt < g_nmt) {
                    do_gemm<KT1, true>(mt, nb, wts, out, sb, tid);
                    __threadfence();
                    __syncthreads();
                    if (tid == 0) atomicAdd(&g_done[mt], 1);
                }
            }
        } else {
            int ti = t - T_FC2, mt = ti >> 3, nb = ti & 7;
            if (tid == 0)
                while (ld_acq(&g_c_wz) != 256) __nanosleep(64);
            __syncthreads();
            if (mt < g_nmt) {
                if (tid == 0)
                    while (ld_acq(&g_done[mt]) != 8) __nanosleep(64);
                __syncthreads();
                do_gemm<KT2, false>(mt, nb, wts, out, sb, tid);
            }
        }
    }
}

// ================= host =================
extern "C" void kernel_launch(void* const* d_in, const int* in_sizes, int n_in,
                              void* d_out, int out_size) {
    const float* x      = (const float*)d_in[0];
    const float* wts    = (const float*)d_in[1];
    const int*   idx    = (const int*)d_in[2];
    const int*   counts = (const int*)d_in[3];
    const float* fc1w   = (const float*)d_in[4];
    const float* fc2w   = (const float*)d_in[5];
    float* out = (float*)d_out;

    cudaFuncSetAttribute(k_persist,
                         cudaFuncAttributeMaxDynamicSharedMemorySize, SMEM_SZ);

    k_persist<<<NGRID, 256, SMEM_SZ>>>(x, fc1w, fc2w, wts, idx, counts, out);
}

// round 11
// speedup vs baseline: 1.3353x; 1.0461x over previous
#include <cuda_runtime.h>
#include <cuda_fp16.h>
#include <cstdint>

#define N_TOK   2048
#define D_MODEL 1024
#define D_INT   512
#define NE      8
#define NPAIR   (N_TOK * 2)
#define NPAD    5120
#define KT1     16                // fc1 k-tiles (K=1024, BK=64)
#define KT2     8                 // fc2 k-tiles (K=512)

#define TILE_A      16384         // 128 rows x 128B fp16
#define TILE_B      16384
#define STAGE_BYTES (TILE_A + TILE_B)
#define NSTAGE      2
#define SMEM_SZ     (1024 + NSTAGE * STAGE_BYTES)   // 66560 -> 2 CTAs/SM

// ---- task queue: setup | x | w1 | fc1 | w2 | zero | fc2 ----
#define T_X    1
#define T_W1   161
#define T_FC1  417
#define T_W2   737
#define T_Z    865
#define T_FC2  993
#define TTOT   1313
#define NGRID  296

// ---- scratch (zero at load; self-reset at exit) ----
__device__ int g_pair[NPAD];
__device__ int g_ticket;
__device__ int g_setup;
__device__ int g_exit;
__device__ int g_c_wz;            // w2+zero done (target 256)
__device__ int g_rdy_a[40];       // per-mtile x-conv done (target 4)
__device__ int g_rdy_b1[64];      // per-(e,nb) w1-conv done (target 4)
__device__ int g_done[64];        // per-mtile fc1 done (target 8)
__device__ int g_nmt;
__device__ int g_mt_e[64];
__device__ int g_mt_rows[64];
__device__ __align__(16) char g_A1[(size_t)(NPAD / 128) * KT1 * TILE_A];
__device__ __align__(16) char g_B1[(size_t)NE * 8 * KT1 * TILE_B];
__device__ __align__(16) char g_A2[(size_t)(NPAD / 128) * KT2 * TILE_A];
__device__ __align__(16) char g_B2[(size_t)NE * 8 * KT2 * TILE_B];

// ================= asm helpers (sm_90-base PTX only) =================
__device__ __forceinline__ uint32_t smem_u32(const void* p) {
    uint32_t a;
    asm("{ .reg .u64 t; cvta.to.shared.u64 t, %1; cvt.u32.u64 %0, t; }" : "=r"(a) : "l"(p));
    return a;
}
__device__ __forceinline__ int ld_acq(const int* p) {
    int v;
    asm volatile("ld.acquire.gpu.global.b32 %0, [%1];" : "=r"(v) : "l"(p) : "memory");
    return v;
}
__device__ __forceinline__ void mbar_init(uint32_t a, uint32_t cnt) {
    asm volatile("mbarrier.init.shared::cta.b64 [%0], %1;" :: "r"(a), "r"(cnt) : "memory");
}
__device__ __forceinline__ void mbar_expect_tx(uint32_t a, uint32_t bytes) {
    asm volatile("mbarrier.arrive.expect_tx.shared::cta.b64 _, [%0], %1;"
                 :: "r"(a), "r"(bytes) : "memory");
}
__device__ __forceinline__ void mwait(uint32_t a, uint32_t ph) {
    asm volatile(
        "{\n\t.reg .pred P;\n"
        "W%=:\n\t"
        "mbarrier.try_wait.parity.acquire.cta.shared::cta.b64 P, [%0], %1, 0x989680;\n\t"
        "@P bra D%=;\n\t"
        "bra W%=;\n"
        "D%=:\n\t}"
        :: "r"(a), "r"(ph) : "memory");
}
__device__ __forceinline__ void bulk_g2s(uint32_t dst, const void* src, uint32_t bytes, uint32_t mbar) {
    asm volatile(
        "cp.async.bulk.shared::cluster.global.mbarrier::complete_tx::bytes [%0], [%1], %2, [%3];"
        :: "r"(dst), "l"(src), "r"(bytes), "r"(mbar) : "memory");
}
__device__ __forceinline__ void ldsm4(uint32_t* r, uint32_t a) {
    asm volatile("ldmatrix.sync.aligned.m8n8.x4.shared.b16 {%0,%1,%2,%3}, [%4];"
                 : "=r"(r[0]), "=r"(r[1]), "=r"(r[2]), "=r"(r[3]) : "r"(a));
}
__device__ __forceinline__ void mma_f16(float* d, const uint32_t* a, const uint32_t* b) {
    asm volatile(
        "mma.sync.aligned.m16n8k16.row.col.f32.f16.f16.f32 "
        "{%0,%1,%2,%3}, {%4,%5,%6,%7}, {%8,%9}, {%0,%1,%2,%3};"
        : "+f"(d[0]), "+f"(d[1]), "+f"(d[2]), "+f"(d[3])
        : "r"(a[0]), "r"(a[1]), "r"(a[2]), "r"(a[3]), "r"(b[0]), "r"(b[1]));
}
__device__ __forceinline__ uint32_t swz128(int row, int chunk) {
    return (uint32_t)(row * 128 + ((chunk ^ (row & 7)) << 4));
}

// ================= GEMM tile; compile-time KT/FC1; NSTAGE=2 ================
template<int KT, bool FC1>
__device__ __forceinline__ void do_gemm(int mt, int nb,
                                        const float* __restrict__ wts,
                                        float* __restrict__ out,
                                        uint32_t sb, int tid) {
    int lane = tid & 31, wid = tid >> 5;
    int e = g_mt_e[mt];
    int rows = g_mt_rows[mt];
    const char* Abuf = FC1 ? g_A1 : g_A2;
    const char* Bbuf = FC1 ? g_B1 : g_B2;
    size_t atile = (size_t)mt * KT;
    size_t btile = (size_t)(e * 8 + nb) * KT;
    const int n0 = nb * 128;
    const int arow0 = mt * 128;

    if (tid == 0) {
#pragma unroll
        for (int s = 0; s < NSTAGE; s++) {
            mbar_expect_tx(sb + s * 8, STAGE_BYTES);
            uint32_t d = sb + 1024 + s * STAGE_BYTES;
            bulk_g2s(d,          Abuf + (atile + s) * TILE_A, TILE_A, sb + s * 8);
            bulk_g2s(d + TILE_A, Bbuf + (btile + s) * TILE_B, TILE_B, sb + s * 8);
        }
    }

    int wm = wid & 1, wn = wid >> 1;
    int m_off = wm * 64, n_off = wn * 32;

    float acc[4][4][4];
#pragma unroll
    for (int i = 0; i < 4; i++)
#pragma unroll
        for (int j = 0; j < 4; j++)
#pragma unroll
            for (int q = 0; q < 4; q++) acc[i][j][q] = 0.f;

    int arow_l = m_off + (lane & 15);
    int akoff  = lane >> 4;
    int brow_l = n_off + (lane & 7) + ((lane >> 4) << 3);
    int bkoff  = (lane >> 3) & 1;

#pragma unroll
    for (int kt = 0; kt < KT; kt++) {
        const int slot = kt & 1;
        const int ph = (kt >> 1) & 1;
        mwait(sb + slot * 8, ph);
        uint32_t base = sb + 1024 + slot * STAGE_BYTES;
#pragma unroll
        for (int ks = 0; ks < 4; ks++) {
            uint32_t ahf[4][4];
            int ak = ks * 2 + akoff;
#pragma unroll
            for (int mf = 0; mf < 4; mf++)
                ldsm4(ahf[mf], base + swz128(arow_l + mf * 16, ak));
            int bk = ks * 2 + bkoff;
#pragma unroll
            for (int ng = 0; ng < 2; ng++) {
                uint32_t bf[4];
                ldsm4(bf, base + TILE_A + swz128(brow_l + ng * 16, bk));
#pragma unroll
                for (int mf = 0; mf < 4; mf++) {
                    mma_f16(acc[mf][2 * ng],     ahf[mf], &bf[0]);
                    mma_f16(acc[mf][2 * ng + 1], ahf[mf], &bf[2]);
                }
            }
        }
        __syncthreads();
        if (kt + NSTAGE < KT) {
            if (tid == 0) {
                mbar_expect_tx(sb + slot * 8, STAGE_BYTES);
                bulk_g2s(base,          Abuf + (atile + kt + NSTAGE) * TILE_A, TILE_A, sb + slot * 8);
                bulk_g2s(base + TILE_A, Bbuf + (btile + kt + NSTAGE) * TILE_B, TILE_B, sb + slot * 8);
            }
        }
    }

    int rq = lane >> 2, cq = lane & 3;
#pragma unroll
    for (int mf = 0; mf < 4; mf++) {
#pragma unroll
        for (int half = 0; half < 2; half++) {
            int mloc = m_off + mf * 16 + rq + half * 8;
            if (mloc >= rows) continue;
            if (FC1) {
                size_t trow = (size_t)mt * KT2;
#pragma unroll
                for (int nt = 0; nt < 4; nt++) {
                    float y = acc[mf][nt][half * 2];
                    float z = acc[mf][nt][half * 2 + 1];
                    float a = y * z * (1.f / (1.f + __expf(-z)));
                    int j = ((n0 + n_off + nt * 8) >> 1) + cq;
                    char* p = g_A2 + (trow + (j >> 6)) * TILE_A
                                  + swz128(mloc, (j >> 3) & 7) + (j & 7) * 2;
                    *(__half*)p = __float2half_rn(a);
                }
            } else {
                int pr = g_pair[arow0 + mloc];
                float w = wts[pr];
                float* ob = out + (size_t)(pr >> 1) * D_MODEL;
#pragma unroll
                for (int nt = 0; nt < 4; nt++) {
                    int nc = n0 + n_off + nt * 8 + cq * 2;
                    atomicAdd(ob + nc,     w * acc[mf][nt][half * 2]);
                    atomicAdd(ob + nc + 1, w * acc[mf][nt][half * 2 + 1]);
                }
            }
        }
    }
}

// ================= single persistent kernel =================
__global__ __launch_bounds__(256, 2) void k_persist(
    const float* __restrict__ x, const float* __restrict__ w1f,
    const float* __restrict__ w2f, const float* __restrict__ wts,
    const int* __restrict__ indices, const int* __restrict__ counts,
    float* __restrict__ out)
{
    extern __shared__ __align__(128) char smem[];
    __shared__ int s_task;
    __shared__ int s_off[NE];
    __shared__ int s_cur[NE];
    uint32_t sb = smem_u32(smem);
    int tid = threadIdx.x;

    if (tid < NSTAGE) mbar_init(sb + tid * 8, 1);
    __syncthreads();
    if (tid == 0)
        asm volatile("fence.proxy.async.shared::cta;" ::: "memory");
    __syncthreads();

    for (;;) {
        __syncthreads();
        if (tid == 0) s_task = atomicAdd(&g_ticket, 1);
        __syncthreads();
        int t = s_task;

        if (t >= TTOT) {
            __syncthreads();
            if (tid == 0) {
                __threadfence();
                int old = atomicAdd(&g_exit, 1);
                if (old == NGRID - 1) {
                    g_ticket = 0; g_c_wz = 0; g_setup = 0; g_exit = 0;
                    for (int i = 0; i < 64; i++) {
                        g_done[i] = 0;
                        g_rdy_b1[i] = 0;
                        if (i < 40) g_rdy_a[i] = 0;
                    }
                    __threadfence();
                }
            }
            return;
        }

        if (t == 0) {
            // ---- setup: mtile table + pair scatter ----
            if (tid == 0) {
                int o = 0, mt = 0;
                for (int e = 0; e < NE; e++) {
                    int c = counts[e];
                    s_off[e] = o;
                    int tiles = (c + 127) >> 7;
                    for (int k = 0; k < tiles; k++) {
                        g_mt_e[mt] = e;
                        int rr = c - k * 128;
                        g_mt_rows[mt] = rr > 128 ? 128 : rr;
                        mt++;
                    }
                    o += tiles << 7;
                }
                g_nmt = mt;
            }
            for (int i = tid; i < NPAD; i += 256) g_pair[i] = -1;
            __syncthreads();
            if (tid < NE) s_cur[tid] = s_off[tid];
            __syncthreads();
            for (int p = tid; p < NPAIR; p += 256) {
                int e = indices[p];
                int pos = atomicAdd(&s_cur[e], 1);
                g_pair[pos] = p;
            }
            __threadfence();
            __syncthreads();
            if (tid == 0) atomicExch(&g_setup, 1);
        } else if (t < T_W1) {
            // ---- x conversion (needs setup); task covers 32 s-rows ----
            if (tid == 0)
                while (ld_acq(&g_setup) == 0) __nanosleep(32);
            __syncthreads();
            int i = t - T_X;
            int base = i * 4096;
#pragma unroll
            for (int it = 0; it < 16; it++) {
                int gid = base + it * 256 + tid;
                int s = gid >> 7;
                int k8 = gid & 127;
                char* dst = g_A1 + (size_t)((s >> 7) * KT1 + (k8 >> 3)) * TILE_A
                                 + swz128(s & 127, k8 & 7);
                int pr = g_pair[s];
                if (pr < 0) {
                    *(uint4*)dst = make_uint4(0, 0, 0, 0);
                    continue;
                }
                const float* sp = x + (size_t)(pr >> 1) * D_MODEL + k8 * 8;
                float f[8];
                *(float4*)&f[0] = *(const float4*)sp;
                *(float4*)&f[4] = *(const float4*)(sp + 4);
                __half h[8];
#pragma unroll
                for (int q = 0; q < 8; q++) h[q] = __float2half_rn(f[q]);
                *(uint4*)dst = *(uint4*)h;
            }
            __threadfence();
            __syncthreads();
            if (tid == 0) atomicAdd(&g_rdy_a[i >> 2], 1);
        } else if (t < T_FC1) {
            // ---- w1 conversion; task j covers 32 n-rows of expert j>>5 ----
            int j = t - T_W1;
            int base = j * 4096;
#pragma unroll
            for (int it = 0; it < 16; it++) {
                int gid = base + it * 256 + tid;
                int e = gid >> 17;
                int rem = gid & 131071;
                int n = rem >> 7;
                int k8 = rem & 127;
                int jj = n >> 1, g = n & 1;
                const float* sp = w1f + (size_t)e * (2 * D_INT * D_MODEL)
                                      + (size_t)(g * D_INT + jj) * D_MODEL + k8 * 8;
                float f[8];
                *(float4*)&f[0] = *(const float4*)sp;
                *(float4*)&f[4] = *(const float4*)(sp + 4);
                __half h[8];
#pragma unroll
                for (int q = 0; q < 8; q++) h[q] = __float2half_rn(f[q]);
                char* dst = g_B1 + (size_t)((e * 8 + (n >> 7)) * KT1 + (k8 >> 3)) * TILE_B
                                + swz128(n & 127, k8 & 7);
                *(uint4*)dst = *(uint4*)h;
            }
            __threadfence();
            __syncthreads();
            if (tid == 0) atomicAdd(&g_rdy_b1[(j >> 5) * 8 + ((j & 31) >> 2)], 1);
        } else if (t < T_W2) {
            // ---- fc1 tile: fine-grained deps ----
            int ti = t - T_FC1, mt = ti >> 3, nb = ti & 7;
            if (tid == 0)
                while (ld_acq(&g_rdy_a[mt]) != 4) __nanosleep(32);
            __syncthreads();
            if (mt < g_nmt) {                       // valid: x deps imply setup
                int e = g_mt_e[mt];
                if (tid == 0)
                    while (ld_acq(&g_rdy_b1[e * 8 + nb]) != 4) __nanosleep(32);
                __syncthreads();
                do_gemm<KT1, true>(mt, nb, wts, out, sb, tid);
                __threadfence();
                __syncthreads();
                if (tid == 0) atomicAdd(&g_done[mt], 1);
            }
        } else if (t < T_Z) {
            // ---- w2 conversion ----
            int base = (t - T_W2) * 4096;
#pragma unroll
            for (int it = 0; it < 16; it++) {
                int gid = base + it * 256 + tid;
                int ee = gid >> 16;
                int rem = gid & 65535;
                int n = rem >> 6;
                int k8 = rem & 63;
                const float* sp = w2f + (size_t)ee * (D_MODEL * D_INT) + (size_t)n * D_INT + k8 * 8;
                float f[8];
                *(float4*)&f[0] = *(const float4*)sp;
                *(float4*)&f[4] = *(const float4*)(sp + 4);
                __half h[8];
#pragma unroll
                for (int q = 0; q < 8; q++) h[q] = __float2half_rn(f[q]);
                char* dst = g_B2 + (size_t)((ee * 8 + (n >> 7)) * KT2 + (k8 >> 3)) * TILE_B
                                + swz128(n & 127, k8 & 7);
                *(uint4*)dst = *(uint4*)h;
            }
            __threadfence();
            __syncthreads();
            if (tid == 0) atomicAdd(&g_c_wz, 1);
        } else if (t < T_FC2) {
            // ---- zero out ----
            int base = (t - T_Z) * 4096;
#pragma unroll
            for (int it = 0; it < 16; it++) {
                int gid = base + it * 256 + tid;
                ((float4*)out)[gid] = make_float4(0.f, 0.f, 0.f, 0.f);
            }
            __threadfence();
            __syncthreads();
            if (tid == 0) atomicAdd(&g_c_wz, 1);
        } else {
            // ---- fc2 tile ----
            int ti = t - T_FC2, mt = ti >> 3, nb = ti & 7;
            if (tid == 0) {
                while (ld_acq(&g_c_wz) != 256) __nanosleep(64);
                while (ld_acq(&g_rdy_a[mt]) != 4) __nanosleep(32);   // setup guard
            }
            __syncthreads();
            if (mt < g_nmt) {
                if (tid == 0)
                    while (ld_acq(&g_done[mt]) != 8) __nanosleep(64);
                __syncthreads();
                do_gemm<KT2, false>(mt, nb, wts, out, sb, tid);
            }
        }
    }
}

// ================= host =================
extern "C" void kernel_launch(void* const* d_in, const int* in_sizes, int n_in,
                              void* d_out, int out_size) {
    const float* x      = (const float*)d_in[0];
    const float* wts    = (const float*)d_in[1];
    const int*   idx    = (const int*)d_in[2];
    const int*   counts = (const int*)d_in[3];
    const float* fc1w   = (const float*)d_in[4];
    const float* fc2w   = (const float*)d_in[5];
    float* out = (float*)d_out;

    cudaFuncSetAttribute(k_persist,
                         cudaFuncAttributeMaxDynamicSharedMemorySize, SMEM_SZ);

    k_persist<<<NGRID, 256, SMEM_SZ>>>(x, fc1w, fc2w, wts, idx, counts, out);
}